// round 1
// baseline (speedup 1.0000x reference)
#include <cuda_runtime.h>
#include <math.h>

#define BB 2
#define SS 2048
#define EE 1024
#define HH 16
#define DKK 64
#define HD (HH*DKK)   // 1024

// -------- scratch (allocation-free rule: __device__ globals) --------
__device__ float g_qh[BB*HH*SS*DKK];   // (B,H,S,DK)
__device__ float g_kh[BB*HH*SS*DKK];
__device__ float g_vh[BB*HH*SS*DKK];
__device__ float g_concat[BB*SS*HD];   // (B*S, H*DK)

// ===================================================================
// Generic 128x128x8 SGEMM, 256 threads, 8x8 per thread.
// MODE 0: C[row*N+col] = acc + bias[col]   (plain row-major)
// MODE 1: scatter to head layout dst[((b*H+h)*S+s)*DK+d], row=b*S+s, col=h*DK+d
// ===================================================================
template<int MODE>
__global__ __launch_bounds__(256) void gemm_k(
    const float* __restrict__ A, const float* __restrict__ Bm,
    const float* __restrict__ bias, float* __restrict__ C,
    int M, int N, int K)
{
    __shared__ float As[8][128];
    __shared__ float Bs[8][132];

    int tid = threadIdx.x;
    int bm = blockIdx.y * 128, bn = blockIdx.x * 128;
    int aRow = tid >> 1,  aCol = (tid & 1) * 4;   // A tile 128x8
    int bRow = tid >> 5,  bCol = (tid & 31) * 4;  // B tile 8x128
    int tr = tid >> 4, tc = tid & 15;

    float acc[8][8];
#pragma unroll
    for (int i = 0; i < 8; i++)
#pragma unroll
        for (int j = 0; j < 8; j++) acc[i][j] = 0.f;

    for (int k0 = 0; k0 < K; k0 += 8) {
        float4 av = *(const float4*)(A + (size_t)(bm + aRow) * K + k0 + aCol);
        As[aCol + 0][aRow] = av.x;
        As[aCol + 1][aRow] = av.y;
        As[aCol + 2][aRow] = av.z;
        As[aCol + 3][aRow] = av.w;
        float4 bv = *(const float4*)(Bm + (size_t)(k0 + bRow) * N + bn + bCol);
        *(float4*)&Bs[bRow][bCol] = bv;
        __syncthreads();
#pragma unroll
        for (int kk = 0; kk < 8; kk++) {
            float4 a0 = *(float4*)&As[kk][tr * 8];
            float4 a1 = *(float4*)&As[kk][tr * 8 + 4];
            float4 b0 = *(float4*)&Bs[kk][tc * 8];
            float4 b1 = *(float4*)&Bs[kk][tc * 8 + 4];
            float a[8] = {a0.x,a0.y,a0.z,a0.w,a1.x,a1.y,a1.z,a1.w};
            float b[8] = {b0.x,b0.y,b0.z,b0.w,b1.x,b1.y,b1.z,b1.w};
#pragma unroll
            for (int i = 0; i < 8; i++)
#pragma unroll
                for (int j = 0; j < 8; j++)
                    acc[i][j] = fmaf(a[i], b[j], acc[i][j]);
        }
        __syncthreads();
    }

    float bb[8];
#pragma unroll
    for (int j = 0; j < 8; j++) bb[j] = bias[bn + tc * 8 + j];

#pragma unroll
    for (int i = 0; i < 8; i++) {
        int row = bm + tr * 8 + i;
        int col = bn + tc * 8;
        float4 w0, w1;
        w0.x = acc[i][0] + bb[0]; w0.y = acc[i][1] + bb[1];
        w0.z = acc[i][2] + bb[2]; w0.w = acc[i][3] + bb[3];
        w1.x = acc[i][4] + bb[4]; w1.y = acc[i][5] + bb[5];
        w1.z = acc[i][6] + bb[6]; w1.w = acc[i][7] + bb[7];
        if (MODE == 0) {
            float* cp = C + (size_t)row * N + col;
            *(float4*)cp = w0;
            *(float4*)(cp + 4) = w1;
        } else {
            int bI = row / SS, sI = row % SS;
            int hI = col >> 6, dI = col & 63;
            float* cp = C + (((size_t)(bI * HH + hI) * SS + sI) * DKK + dI);
            *(float4*)cp = w0;
            *(float4*)(cp + 4) = w1;
        }
    }
}

// ===================================================================
// Fused attention: per (b, h, 64-row q tile)
//   loop over 128-wide K tiles: S = Q@K^T * 0.125, mask, write scores,
//   online softmax, O += P@V.  Scores written exactly once, never re-read.
// ===================================================================
#define BQ 64
#define BKV 128

// smem layout (floats):
//   QsT [64][68]     (d-major: QsT[d][q])           4352
//   KP  [64][132]    K^T tile, later reused as P    8448
//   Vs  [128][68]                                   8704
//   maskS[128] (int)                                 128
//   red [64][4]                                      256
//   m_s[64] l_s[64] al_s[64]                         192
#define SM_QST 0
#define SM_KP  (SM_QST + 64*68)
#define SM_VS  (SM_KP  + 64*132)
#define SM_MSK (SM_VS  + 128*68)
#define SM_RED (SM_MSK + 128)
#define SM_M   (SM_RED + 256)
#define SM_L   (SM_M + 64)
#define SM_AL  (SM_L + 64)
#define SM_FLOATS (SM_AL + 64)

__global__ __launch_bounds__(256) void attn_k(
    const float* __restrict__ qh, const float* __restrict__ kh,
    const float* __restrict__ vh, const int* __restrict__ mask,
    float* __restrict__ scores, float* __restrict__ concat)
{
    extern __shared__ float sm[];
    float* QsT = sm + SM_QST;
    float* KP  = sm + SM_KP;
    float* Vs  = sm + SM_VS;
    int*   mkS = (int*)(sm + SM_MSK);
    float* red = sm + SM_RED;
    float* m_s = sm + SM_M;
    float* l_s = sm + SM_L;
    float* al_s= sm + SM_AL;

    int tid = threadIdx.x;
    int q0 = blockIdx.x * BQ;
    int h = blockIdx.y, b = blockIdx.z;

    const float* Qb = qh + (size_t)(b * HH + h) * SS * DKK;
    const float* Kb = kh + (size_t)(b * HH + h) * SS * DKK;
    const float* Vb = vh + (size_t)(b * HH + h) * SS * DKK;
    float* scb = scores + ((size_t)(b * HH + h) * SS + q0) * SS;

    // load Q tile transposed (one time)
#pragma unroll
    for (int p = 0; p < 4; p++) {
        int q = p * 16 + (tid >> 4);
        int d = (tid & 15) * 4;
        float4 v = *(const float4*)(Qb + (size_t)(q0 + q) * DKK + d);
        QsT[(d + 0) * 68 + q] = v.x;
        QsT[(d + 1) * 68 + q] = v.y;
        QsT[(d + 2) * 68 + q] = v.z;
        QsT[(d + 3) * 68 + q] = v.w;
    }
    if (tid < 64) { m_s[tid] = -INFINITY; l_s[tid] = 0.f; }

    int tr = tid >> 4, tc = tid & 15;
    float o[4][4];
#pragma unroll
    for (int i = 0; i < 4; i++)
#pragma unroll
        for (int j = 0; j < 4; j++) o[i][j] = 0.f;

    __syncthreads();

    for (int kv0 = 0; kv0 < SS; kv0 += BKV) {
        // ---- load K (transposed) and V tiles ----
#pragma unroll
        for (int p = 0; p < 8; p++) {
            int kv = p * 16 + (tid >> 4);
            int d = (tid & 15) * 4;
            float4 kq = *(const float4*)(Kb + (size_t)(kv0 + kv) * DKK + d);
            KP[(d + 0) * 132 + kv] = kq.x;
            KP[(d + 1) * 132 + kv] = kq.y;
            KP[(d + 2) * 132 + kv] = kq.z;
            KP[(d + 3) * 132 + kv] = kq.w;
            float4 vq = *(const float4*)(Vb + (size_t)(kv0 + kv) * DKK + d);
            *(float4*)&Vs[kv * 68 + d] = vq;
        }
        if (tid < 128) mkS[tid] = mask[b * SS + kv0 + tid];
        __syncthreads();

        // ---- S = Q @ K^T ----
        float s[4][8];
#pragma unroll
        for (int i = 0; i < 4; i++)
#pragma unroll
            for (int j = 0; j < 8; j++) s[i][j] = 0.f;

#pragma unroll
        for (int d = 0; d < DKK; d++) {
            float4 a = *(float4*)&QsT[d * 68 + tr * 4];
            float4 b0 = *(float4*)&KP[d * 132 + tc * 8];
            float4 b1 = *(float4*)&KP[d * 132 + tc * 8 + 4];
            float av[4] = {a.x, a.y, a.z, a.w};
            float bv[8] = {b0.x,b0.y,b0.z,b0.w,b1.x,b1.y,b1.z,b1.w};
#pragma unroll
            for (int i = 0; i < 4; i++)
#pragma unroll
                for (int j = 0; j < 8; j++)
                    s[i][j] = fmaf(av[i], bv[j], s[i][j]);
        }

        // ---- scale + mask + write scores tile ----
#pragma unroll
        for (int i = 0; i < 4; i++) {
#pragma unroll
            for (int j = 0; j < 8; j++) {
                int mv = mkS[tc * 8 + j];
                s[i][j] = mv ? s[i][j] * 0.125f : -1e9f;
            }
            int qr = tr * 4 + i;
            float4 w0 = {s[i][0], s[i][1], s[i][2], s[i][3]};
            float4 w1 = {s[i][4], s[i][5], s[i][6], s[i][7]};
            float* sp = scb + (size_t)qr * SS + kv0 + tc * 8;
            *(float4*)sp = w0;
            *(float4*)(sp + 4) = w1;
        }
        __syncthreads();   // all threads done reading KP as K

        // ---- store P-raw into KP as [q][132] ----
#pragma unroll
        for (int i = 0; i < 4; i++) {
            float4 w0 = {s[i][0], s[i][1], s[i][2], s[i][3]};
            float4 w1 = {s[i][4], s[i][5], s[i][6], s[i][7]};
            *(float4*)&KP[(tr * 4 + i) * 132 + tc * 8] = w0;
            *(float4*)&KP[(tr * 4 + i) * 132 + tc * 8 + 4] = w1;
        }
        __syncthreads();

        // ---- row max (4 threads per row) ----
        int r = tid >> 2, sg = tid & 3;
        {
            float mx = -INFINITY;
#pragma unroll 8
            for (int c = 0; c < 32; c++)
                mx = fmaxf(mx, KP[r * 132 + sg * 32 + c]);
            red[r * 4 + sg] = mx;
        }
        __syncthreads();
        if (sg == 0) {
            float tmax = fmaxf(fmaxf(red[r*4], red[r*4+1]),
                               fmaxf(red[r*4+2], red[r*4+3]));
            float mo = m_s[r];
            float mn = fmaxf(mo, tmax);
            al_s[r] = __expf(mo - mn);
            m_s[r] = mn;
        }
        __syncthreads();

        // ---- exp pass + partial sums ----
        {
            float mn = m_s[r];
            float sum = 0.f;
#pragma unroll 8
            for (int c = 0; c < 32; c++) {
                float p = __expf(KP[r * 132 + sg * 32 + c] - mn);
                KP[r * 132 + sg * 32 + c] = p;
                sum += p;
            }
            red[r * 4 + sg] = sum;
        }
        __syncthreads();
        if (sg == 0)
            l_s[r] = l_s[r] * al_s[r] +
                     (red[r*4] + red[r*4+1] + red[r*4+2] + red[r*4+3]);

        // ---- rescale O ----
#pragma unroll
        for (int i = 0; i < 4; i++) {
            float a_ = al_s[tr * 4 + i];
#pragma unroll
            for (int j = 0; j < 4; j++) o[i][j] *= a_;
        }

        // ---- O += P @ V ----
#pragma unroll 4
        for (int kv = 0; kv < BKV; kv += 4) {
            float pa[4][4];
#pragma unroll
            for (int i = 0; i < 4; i++) {
                float4 aq = *(float4*)&KP[(tr * 4 + i) * 132 + kv];
                pa[i][0] = aq.x; pa[i][1] = aq.y; pa[i][2] = aq.z; pa[i][3] = aq.w;
            }
#pragma unroll
            for (int l = 0; l < 4; l++) {
                float4 bq = *(float4*)&Vs[(kv + l) * 68 + tc * 4];
                float bvv[4] = {bq.x, bq.y, bq.z, bq.w};
#pragma unroll
                for (int i = 0; i < 4; i++)
#pragma unroll
                    for (int j = 0; j < 4; j++)
                        o[i][j] = fmaf(pa[i][l], bvv[j], o[i][j]);
            }
        }
        __syncthreads();  // before next iteration overwrites KP / stats
    }

    // ---- finalize: divide by l, write to concat layout ----
#pragma unroll
    for (int i = 0; i < 4; i++) {
        float inv = 1.f / l_s[tr * 4 + i];
        int qg = q0 + tr * 4 + i;
        float4 w = {o[i][0] * inv, o[i][1] * inv, o[i][2] * inv, o[i][3] * inv};
        *(float4*)(concat + (size_t)(b * SS + qg) * HD + h * DKK + tc * 4) = w;
    }
}

// ===================================================================
extern "C" void kernel_launch(void* const* d_in, const int* in_sizes, int n_in,
                              void* d_out, int out_size)
{
    const float* q   = (const float*)d_in[0];
    const float* k   = (const float*)d_in[1];
    const float* v   = (const float*)d_in[2];
    const int*   msk = (const int*)  d_in[3];
    const float* Wq  = (const float*)d_in[4];
    const float* bq  = (const float*)d_in[5];
    const float* Wk  = (const float*)d_in[6];
    const float* bk  = (const float*)d_in[7];
    const float* Wv  = (const float*)d_in[8];
    const float* bv  = (const float*)d_in[9];
    const float* Wo  = (const float*)d_in[10];
    const float* bo  = (const float*)d_in[11];

    float* out    = (float*)d_out;              // (B,S,E)
    float* scores = out + (size_t)BB * SS * EE; // (B,H,S,S)

    float *p_qh, *p_kh, *p_vh, *p_cc;
    cudaGetSymbolAddress((void**)&p_qh, g_qh);
    cudaGetSymbolAddress((void**)&p_kh, g_kh);
    cudaGetSymbolAddress((void**)&p_vh, g_vh);
    cudaGetSymbolAddress((void**)&p_cc, g_concat);

    dim3 gProj(HD / 128, (BB * SS) / 128);  // (8, 32)
    gemm_k<1><<<gProj, 256>>>(q, Wq, bq, p_qh, BB * SS, HD, EE);
    gemm_k<1><<<gProj, 256>>>(k, Wk, bk, p_kh, BB * SS, HD, EE);
    gemm_k<1><<<gProj, 256>>>(v, Wv, bv, p_vh, BB * SS, HD, EE);

    int smemBytes = SM_FLOATS * (int)sizeof(float);
    cudaFuncSetAttribute(attn_k, cudaFuncAttributeMaxDynamicSharedMemorySize,
                         smemBytes);
    dim3 gAttn(SS / BQ, HH, BB);            // (32, 16, 2)
    attn_k<<<gAttn, 256, smemBytes>>>(p_qh, p_kh, p_vh, msk, scores, p_cc);

    dim3 gOut(EE / 128, (BB * SS) / 128);   // (8, 32)
    gemm_k<0><<<gOut, 256>>>(p_cc, Wo, bo, out, BB * SS, EE, HD);
}

// round 3
// speedup vs baseline: 1.2548x; 1.2548x over previous
#include <cuda_runtime.h>
#include <math.h>
#include <stdint.h>

#define BB 2
#define SS 2048
#define EE 1024
#define HH 16
#define DKK 64
#define HD (HH*DKK)   // 1024

// -------- scratch (allocation-free rule: __device__ globals) --------
__device__ float g_qh[BB*HH*SS*DKK];   // (B,H,S,DK)
__device__ float g_kh[BB*HH*SS*DKK];
__device__ float g_vh[BB*HH*SS*DKK];
__device__ float g_concat[BB*SS*HD];   // (B*S, H*DK)

// ===================================================================
// mma.sync tf32 helpers (baseline PTX, works on compute_103)
// ===================================================================
__device__ __forceinline__ uint32_t f2tf32(float f) {
    uint32_t r;
    asm("cvt.rna.tf32.f32 %0, %1;" : "=r"(r) : "f"(f));
    return r;
}

__device__ __forceinline__ void mma_tf32(float* d, const uint32_t* a,
                                         const uint32_t* b) {
    asm volatile(
        "mma.sync.aligned.m16n8k8.row.col.f32.tf32.tf32.f32 "
        "{%0,%1,%2,%3}, {%4,%5,%6,%7}, {%8,%9}, {%0,%1,%2,%3};"
        : "+f"(d[0]), "+f"(d[1]), "+f"(d[2]), "+f"(d[3])
        : "r"(a[0]), "r"(a[1]), "r"(a[2]), "r"(a[3]),
          "r"(b[0]), "r"(b[1]));
}

// ===================================================================
// tf32 tensor-core GEMM: C[M,N] = A[M,K] @ W[K,N] + bias
// 128x128 block, 8 warps (32x64 warp tile), K-chunk 32, double buffer.
// MODE 0: row-major store.  MODE 1: scatter to (B,H,S,DK) head layout.
// Smem: As m-major stride 44 (conflict-free frag LDS + STS.128),
//       Bs k-major stride 136 (direct copy of W rows, conflict-free).
// ===================================================================
#define GSTRA 44
#define GSTRB 136
#define ASZ (128*GSTRA)          // u32 words per A buffer (5632)
#define BSZ (32*GSTRB)           // u32 words per B buffer (4352)
#define GEMM_SMEM_BYTES ((2*ASZ + 2*BSZ) * 4)   // 79872

template<int MODE>
__global__ __launch_bounds__(256)
void gemm_mma(const float* __restrict__ A, const float* __restrict__ W,
              const float* __restrict__ bias, float* __restrict__ C,
              int M, int N, int K)
{
    extern __shared__ uint32_t sm[];
    uint32_t* AsBuf[2] = { sm,           sm + ASZ };
    uint32_t* BsBuf[2] = { sm + 2*ASZ,   sm + 2*ASZ + BSZ };

    int tid = threadIdx.x, lane = tid & 31, wid = tid >> 5;
    int bm = blockIdx.y * 128, bn = blockIdx.x * 128;
    int wM = (wid >> 1) * 32, wN = (wid & 1) * 64;
    int g = lane >> 2, c = lane & 3;

    float acc[2][8][4];
#pragma unroll
    for (int mf = 0; mf < 2; mf++)
#pragma unroll
        for (int nf = 0; nf < 8; nf++)
#pragma unroll
            for (int r = 0; r < 4; r++) acc[mf][nf][r] = 0.f;

    const int NC = K / 32;

    // per-thread load coordinates
    int aM = tid >> 3, aK4 = tid & 7;     // + it*32 rows
    int bK = tid >> 5, bN4 = tid & 31;    // + it*8  k-rows

    float4 aR[4], bR[4];

    // ---- prologue: chunk 0 ----
#pragma unroll
    for (int it = 0; it < 4; it++) {
        aR[it] = *(const float4*)(A + (size_t)(bm + aM + it*32) * K + aK4 * 4);
        bR[it] = *(const float4*)(W + (size_t)(bK + it*8) * N + bn + bN4 * 4);
    }
#pragma unroll
    for (int it = 0; it < 4; it++) {
        uint4 ta = { f2tf32(aR[it].x), f2tf32(aR[it].y),
                     f2tf32(aR[it].z), f2tf32(aR[it].w) };
        *(uint4*)(AsBuf[0] + (aM + it*32) * GSTRA + aK4 * 4) = ta;
        uint4 tb = { f2tf32(bR[it].x), f2tf32(bR[it].y),
                     f2tf32(bR[it].z), f2tf32(bR[it].w) };
        *(uint4*)(BsBuf[0] + (bK + it*8) * GSTRB + bN4 * 4) = tb;
    }
    __syncthreads();

    for (int i = 0; i < NC; i++) {
        int buf = i & 1;
        // ---- prefetch next chunk ----
        if (i + 1 < NC) {
#pragma unroll
            for (int it = 0; it < 4; it++) {
                aR[it] = *(const float4*)(A + (size_t)(bm + aM + it*32) * K
                                          + (i+1) * 32 + aK4 * 4);
                bR[it] = *(const float4*)(W + (size_t)((i+1) * 32 + bK + it*8) * N
                                          + bn + bN4 * 4);
            }
        }

        // ---- compute this chunk: 4 k-steps of k8 ----
        const uint32_t* as = AsBuf[buf];
        const uint32_t* bs = BsBuf[buf];
#pragma unroll
        for (int ks = 0; ks < 4; ks++) {
            int kb = ks * 8;
            uint32_t af[2][4], bf[8][2];
#pragma unroll
            for (int mf = 0; mf < 2; mf++) {
                int m = wM + mf * 16 + g;
                af[mf][0] = as[(m    ) * GSTRA + kb + c];
                af[mf][1] = as[(m + 8) * GSTRA + kb + c];
                af[mf][2] = as[(m    ) * GSTRA + kb + c + 4];
                af[mf][3] = as[(m + 8) * GSTRA + kb + c + 4];
            }
#pragma unroll
            for (int nf = 0; nf < 8; nf++) {
                int n = wN + nf * 8 + g;
                bf[nf][0] = bs[(kb + c    ) * GSTRB + n];
                bf[nf][1] = bs[(kb + c + 4) * GSTRB + n];
            }
#pragma unroll
            for (int mf = 0; mf < 2; mf++)
#pragma unroll
                for (int nf = 0; nf < 8; nf++)
                    mma_tf32(acc[mf][nf], af[mf], bf[nf]);
        }

        // ---- stage next chunk into the other buffer ----
        if (i + 1 < NC) {
            __syncthreads();   // everyone done reading buf^1 (iter i-1)
            int nb = buf ^ 1;
#pragma unroll
            for (int it = 0; it < 4; it++) {
                uint4 ta = { f2tf32(aR[it].x), f2tf32(aR[it].y),
                             f2tf32(aR[it].z), f2tf32(aR[it].w) };
                *(uint4*)(AsBuf[nb] + (aM + it*32) * GSTRA + aK4 * 4) = ta;
                uint4 tb = { f2tf32(bR[it].x), f2tf32(bR[it].y),
                             f2tf32(bR[it].z), f2tf32(bR[it].w) };
                *(uint4*)(BsBuf[nb] + (bK + it*8) * GSTRB + bN4 * 4) = tb;
            }
            __syncthreads();
        }
    }

    // ---- epilogue: acc frags + bias -> C ----
#pragma unroll
    for (int nf = 0; nf < 8; nf++) {
        int col = bn + wN + nf * 8 + 2 * c;
        float b0 = bias[col], b1 = bias[col + 1];
#pragma unroll
        for (int mf = 0; mf < 2; mf++) {
            int row = bm + wM + mf * 16 + g;
#pragma unroll
            for (int half = 0; half < 2; half++) {
                int r = row + half * 8;
                float2 w;
                w.x = acc[mf][nf][half * 2 + 0] + b0;
                w.y = acc[mf][nf][half * 2 + 1] + b1;
                float* dst;
                if (MODE == 0) {
                    dst = C + (size_t)r * N + col;
                } else {
                    int bI = r >> 11, sI = r & 2047;
                    int hI = col >> 6, dI = col & 63;
                    dst = C + (((size_t)(bI * HH + hI) * SS + sI) * DKK + dI);
                }
                *(float2*)dst = w;
            }
        }
    }
}

// ===================================================================
// Fused attention (unchanged SIMT fp32 — known good from R1)
// ===================================================================
#define BQ 64
#define BKV 128

#define SM_QST 0
#define SM_KP  (SM_QST + 64*68)
#define SM_VS  (SM_KP  + 64*132)
#define SM_MSK (SM_VS  + 128*68)
#define SM_RED (SM_MSK + 128)
#define SM_M   (SM_RED + 256)
#define SM_L   (SM_M + 64)
#define SM_AL  (SM_L + 64)
#define SM_FLOATS (SM_AL + 64)

__global__ __launch_bounds__(256) void attn_k(
    const float* __restrict__ qh, const float* __restrict__ kh,
    const float* __restrict__ vh, const int* __restrict__ mask,
    float* __restrict__ scores, float* __restrict__ concat)
{
    extern __shared__ float smf[];
    float* QsT = smf + SM_QST;
    float* KP  = smf + SM_KP;
    float* Vs  = smf + SM_VS;
    int*   mkS = (int*)(smf + SM_MSK);
    float* red = smf + SM_RED;
    float* m_s = smf + SM_M;
    float* l_s = smf + SM_L;
    float* al_s= smf + SM_AL;

    int tid = threadIdx.x;
    int q0 = blockIdx.x * BQ;
    int h = blockIdx.y, b = blockIdx.z;

    const float* Qb = qh + (size_t)(b * HH + h) * SS * DKK;
    const float* Kb = kh + (size_t)(b * HH + h) * SS * DKK;
    const float* Vb = vh + (size_t)(b * HH + h) * SS * DKK;
    float* scb = scores + ((size_t)(b * HH + h) * SS + q0) * SS;

#pragma unroll
    for (int p = 0; p < 4; p++) {
        int q = p * 16 + (tid >> 4);
        int d = (tid & 15) * 4;
        float4 v = *(const float4*)(Qb + (size_t)(q0 + q) * DKK + d);
        QsT[(d + 0) * 68 + q] = v.x;
        QsT[(d + 1) * 68 + q] = v.y;
        QsT[(d + 2) * 68 + q] = v.z;
        QsT[(d + 3) * 68 + q] = v.w;
    }
    if (tid < 64) { m_s[tid] = -INFINITY; l_s[tid] = 0.f; }

    int tr = tid >> 4, tc = tid & 15;
    float o[4][4];
#pragma unroll
    for (int i = 0; i < 4; i++)
#pragma unroll
        for (int j = 0; j < 4; j++) o[i][j] = 0.f;

    __syncthreads();

    for (int kv0 = 0; kv0 < SS; kv0 += BKV) {
#pragma unroll
        for (int p = 0; p < 8; p++) {
            int kv = p * 16 + (tid >> 4);
            int d = (tid & 15) * 4;
            float4 kq = *(const float4*)(Kb + (size_t)(kv0 + kv) * DKK + d);
            KP[(d + 0) * 132 + kv] = kq.x;
            KP[(d + 1) * 132 + kv] = kq.y;
            KP[(d + 2) * 132 + kv] = kq.z;
            KP[(d + 3) * 132 + kv] = kq.w;
            float4 vq = *(const float4*)(Vb + (size_t)(kv0 + kv) * DKK + d);
            *(float4*)&Vs[kv * 68 + d] = vq;
        }
        if (tid < 128) mkS[tid] = mask[b * SS + kv0 + tid];
        __syncthreads();

        float s[4][8];
#pragma unroll
        for (int i = 0; i < 4; i++)
#pragma unroll
            for (int j = 0; j < 8; j++) s[i][j] = 0.f;

#pragma unroll
        for (int d = 0; d < DKK; d++) {
            float4 a = *(float4*)&QsT[d * 68 + tr * 4];
            float4 b0 = *(float4*)&KP[d * 132 + tc * 8];
            float4 b1 = *(float4*)&KP[d * 132 + tc * 8 + 4];
            float av[4] = {a.x, a.y, a.z, a.w};
            float bv[8] = {b0.x,b0.y,b0.z,b0.w,b1.x,b1.y,b1.z,b1.w};
#pragma unroll
            for (int i = 0; i < 4; i++)
#pragma unroll
                for (int j = 0; j < 8; j++)
                    s[i][j] = fmaf(av[i], bv[j], s[i][j]);
        }

#pragma unroll
        for (int i = 0; i < 4; i++) {
#pragma unroll
            for (int j = 0; j < 8; j++) {
                int mv = mkS[tc * 8 + j];
                s[i][j] = mv ? s[i][j] * 0.125f : -1e9f;
            }
            int qr = tr * 4 + i;
            float4 w0 = {s[i][0], s[i][1], s[i][2], s[i][3]};
            float4 w1 = {s[i][4], s[i][5], s[i][6], s[i][7]};
            float* sp = scb + (size_t)qr * SS + kv0 + tc * 8;
            *(float4*)sp = w0;
            *(float4*)(sp + 4) = w1;
        }
        __syncthreads();

#pragma unroll
        for (int i = 0; i < 4; i++) {
            float4 w0 = {s[i][0], s[i][1], s[i][2], s[i][3]};
            float4 w1 = {s[i][4], s[i][5], s[i][6], s[i][7]};
            *(float4*)&KP[(tr * 4 + i) * 132 + tc * 8] = w0;
            *(float4*)&KP[(tr * 4 + i) * 132 + tc * 8 + 4] = w1;
        }
        __syncthreads();

        int r = tid >> 2, sg = tid & 3;
        {
            float mx = -INFINITY;
#pragma unroll 8
            for (int cc = 0; cc < 32; cc++)
                mx = fmaxf(mx, KP[r * 132 + sg * 32 + cc]);
            red[r * 4 + sg] = mx;
        }
        __syncthreads();
        if (sg == 0) {
            float tmax = fmaxf(fmaxf(red[r*4], red[r*4+1]),
                               fmaxf(red[r*4+2], red[r*4+3]));
            float mo = m_s[r];
            float mn = fmaxf(mo, tmax);
            al_s[r] = __expf(mo - mn);
            m_s[r] = mn;
        }
        __syncthreads();

        {
            float mn = m_s[r];
            float sum = 0.f;
#pragma unroll 8
            for (int cc = 0; cc < 32; cc++) {
                float p = __expf(KP[r * 132 + sg * 32 + cc] - mn);
                KP[r * 132 + sg * 32 + cc] = p;
                sum += p;
            }
            red[r * 4 + sg] = sum;
        }
        __syncthreads();
        if (sg == 0)
            l_s[r] = l_s[r] * al_s[r] +
                     (red[r*4] + red[r*4+1] + red[r*4+2] + red[r*4+3]);

#pragma unroll
        for (int i = 0; i < 4; i++) {
            float a_ = al_s[tr * 4 + i];
#pragma unroll
            for (int j = 0; j < 4; j++) o[i][j] *= a_;
        }

#pragma unroll 4
        for (int kv = 0; kv < BKV; kv += 4) {
            float pa[4][4];
#pragma unroll
            for (int i = 0; i < 4; i++) {
                float4 aq = *(float4*)&KP[(tr * 4 + i) * 132 + kv];
                pa[i][0] = aq.x; pa[i][1] = aq.y; pa[i][2] = aq.z; pa[i][3] = aq.w;
            }
#pragma unroll
            for (int l = 0; l < 4; l++) {
                float4 bq = *(float4*)&Vs[(kv + l) * 68 + tc * 4];
                float bvv[4] = {bq.x, bq.y, bq.z, bq.w};
#pragma unroll
                for (int i = 0; i < 4; i++)
#pragma unroll
                    for (int j = 0; j < 4; j++)
                        o[i][j] = fmaf(pa[i][l], bvv[j], o[i][j]);
            }
        }
        __syncthreads();
    }

#pragma unroll
    for (int i = 0; i < 4; i++) {
        float inv = 1.f / l_s[tr * 4 + i];
        int qg = q0 + tr * 4 + i;
        float4 w = {o[i][0] * inv, o[i][1] * inv, o[i][2] * inv, o[i][3] * inv};
        *(float4*)(concat + (size_t)(b * SS + qg) * HD + h * DKK + tc * 4) = w;
    }
}

// ===================================================================
extern "C" void kernel_launch(void* const* d_in, const int* in_sizes, int n_in,
                              void* d_out, int out_size)
{
    const float* q   = (const float*)d_in[0];
    const float* k   = (const float*)d_in[1];
    const float* v   = (const float*)d_in[2];
    const int*   msk = (const int*)  d_in[3];
    const float* Wq  = (const float*)d_in[4];
    const float* bq  = (const float*)d_in[5];
    const float* Wk  = (const float*)d_in[6];
    const float* bk  = (const float*)d_in[7];
    const float* Wv  = (const float*)d_in[8];
    const float* bv  = (const float*)d_in[9];
    const float* Wo  = (const float*)d_in[10];
    const float* bo  = (const float*)d_in[11];

    float* out    = (float*)d_out;              // (B,S,E)
    float* scores = out + (size_t)BB * SS * EE; // (B,H,S,S)

    float *p_qh, *p_kh, *p_vh, *p_cc;
    cudaGetSymbolAddress((void**)&p_qh, g_qh);
    cudaGetSymbolAddress((void**)&p_kh, g_kh);
    cudaGetSymbolAddress((void**)&p_vh, g_vh);
    cudaGetSymbolAddress((void**)&p_cc, g_concat);

    cudaFuncSetAttribute(gemm_mma<0>, cudaFuncAttributeMaxDynamicSharedMemorySize,
                         GEMM_SMEM_BYTES);
    cudaFuncSetAttribute(gemm_mma<1>, cudaFuncAttributeMaxDynamicSharedMemorySize,
                         GEMM_SMEM_BYTES);

    dim3 gProj(HD / 128, (BB * SS) / 128);  // (8, 32)
    gemm_mma<1><<<gProj, 256, GEMM_SMEM_BYTES>>>(q, Wq, bq, p_qh, BB * SS, HD, EE);
    gemm_mma<1><<<gProj, 256, GEMM_SMEM_BYTES>>>(k, Wk, bk, p_kh, BB * SS, HD, EE);
    gemm_mma<1><<<gProj, 256, GEMM_SMEM_BYTES>>>(v, Wv, bv, p_vh, BB * SS, HD, EE);

    int smemBytes = SM_FLOATS * (int)sizeof(float);
    cudaFuncSetAttribute(attn_k, cudaFuncAttributeMaxDynamicSharedMemorySize,
                         smemBytes);
    dim3 gAttn(SS / BQ, HH, BB);            // (32, 16, 2)
    attn_k<<<gAttn, 256, smemBytes>>>(p_qh, p_kh, p_vh, msk, scores, p_cc);

    dim3 gOut(EE / 128, (BB * SS) / 128);   // (8, 32)
    gemm_mma<0><<<gOut, 256, GEMM_SMEM_BYTES>>>(p_cc, Wo, bo, out, BB * SS, EE, HD);
}

// round 4
// speedup vs baseline: 2.8861x; 2.3001x over previous
#include <cuda_runtime.h>
#include <math.h>
#include <stdint.h>

#define BB 2
#define SS 2048
#define EE 1024
#define HH 16
#define DKK 64
#define HD (HH*DKK)   // 1024

// -------- scratch (allocation-free rule: __device__ globals) --------
__device__ float g_qh[BB*HH*SS*DKK];   // (B,H,S,DK)
__device__ float g_kh[BB*HH*SS*DKK];
__device__ float g_vh[BB*HH*SS*DKK];
__device__ float g_concat[BB*SS*HD];   // (B*S, H*DK)

// ===================================================================
// mma.sync tf32 helpers (baseline PTX, works on compute_103)
// ===================================================================
__device__ __forceinline__ uint32_t f2tf32(float f) {
    uint32_t r;
    asm("cvt.rna.tf32.f32 %0, %1;" : "=r"(r) : "f"(f));
    return r;
}

__device__ __forceinline__ void mma_tf32(float* d, const uint32_t* a,
                                         const uint32_t* b) {
    asm volatile(
        "mma.sync.aligned.m16n8k8.row.col.f32.tf32.tf32.f32 "
        "{%0,%1,%2,%3}, {%4,%5,%6,%7}, {%8,%9}, {%0,%1,%2,%3};"
        : "+f"(d[0]), "+f"(d[1]), "+f"(d[2]), "+f"(d[3])
        : "r"(a[0]), "r"(a[1]), "r"(a[2]), "r"(a[3]),
          "r"(b[0]), "r"(b[1]));
}

// ===================================================================
// tf32 tensor-core GEMM (unchanged from R3 — verified)
// ===================================================================
#define GSTRA 44
#define GSTRB 136
#define ASZ (128*GSTRA)
#define BSZ (32*GSTRB)
#define GEMM_SMEM_BYTES ((2*ASZ + 2*BSZ) * 4)   // 79872

template<int MODE>
__global__ __launch_bounds__(256)
void gemm_mma(const float* __restrict__ A, const float* __restrict__ W,
              const float* __restrict__ bias, float* __restrict__ C,
              int M, int N, int K)
{
    extern __shared__ uint32_t sm[];
    uint32_t* AsBuf[2] = { sm,           sm + ASZ };
    uint32_t* BsBuf[2] = { sm + 2*ASZ,   sm + 2*ASZ + BSZ };

    int tid = threadIdx.x, lane = tid & 31, wid = tid >> 5;
    int bm = blockIdx.y * 128, bn = blockIdx.x * 128;
    int wM = (wid >> 1) * 32, wN = (wid & 1) * 64;
    int g = lane >> 2, c = lane & 3;

    float acc[2][8][4];
#pragma unroll
    for (int mf = 0; mf < 2; mf++)
#pragma unroll
        for (int nf = 0; nf < 8; nf++)
#pragma unroll
            for (int r = 0; r < 4; r++) acc[mf][nf][r] = 0.f;

    const int NC = K / 32;
    int aM = tid >> 3, aK4 = tid & 7;
    int bK = tid >> 5, bN4 = tid & 31;
    float4 aR[4], bR[4];

#pragma unroll
    for (int it = 0; it < 4; it++) {
        aR[it] = *(const float4*)(A + (size_t)(bm + aM + it*32) * K + aK4 * 4);
        bR[it] = *(const float4*)(W + (size_t)(bK + it*8) * N + bn + bN4 * 4);
    }
#pragma unroll
    for (int it = 0; it < 4; it++) {
        uint4 ta = { f2tf32(aR[it].x), f2tf32(aR[it].y),
                     f2tf32(aR[it].z), f2tf32(aR[it].w) };
        *(uint4*)(AsBuf[0] + (aM + it*32) * GSTRA + aK4 * 4) = ta;
        uint4 tb = { f2tf32(bR[it].x), f2tf32(bR[it].y),
                     f2tf32(bR[it].z), f2tf32(bR[it].w) };
        *(uint4*)(BsBuf[0] + (bK + it*8) * GSTRB + bN4 * 4) = tb;
    }
    __syncthreads();

    for (int i = 0; i < NC; i++) {
        int buf = i & 1;
        if (i + 1 < NC) {
#pragma unroll
            for (int it = 0; it < 4; it++) {
                aR[it] = *(const float4*)(A + (size_t)(bm + aM + it*32) * K
                                          + (i+1) * 32 + aK4 * 4);
                bR[it] = *(const float4*)(W + (size_t)((i+1) * 32 + bK + it*8) * N
                                          + bn + bN4 * 4);
            }
        }

        const uint32_t* as = AsBuf[buf];
        const uint32_t* bs = BsBuf[buf];
#pragma unroll
        for (int ks = 0; ks < 4; ks++) {
            int kb = ks * 8;
            uint32_t af[2][4], bf[8][2];
#pragma unroll
            for (int mf = 0; mf < 2; mf++) {
                int m = wM + mf * 16 + g;
                af[mf][0] = as[(m    ) * GSTRA + kb + c];
                af[mf][1] = as[(m + 8) * GSTRA + kb + c];
                af[mf][2] = as[(m    ) * GSTRA + kb + c + 4];
                af[mf][3] = as[(m + 8) * GSTRA + kb + c + 4];
            }
#pragma unroll
            for (int nf = 0; nf < 8; nf++) {
                int n = wN + nf * 8 + g;
                bf[nf][0] = bs[(kb + c    ) * GSTRB + n];
                bf[nf][1] = bs[(kb + c + 4) * GSTRB + n];
            }
#pragma unroll
            for (int mf = 0; mf < 2; mf++)
#pragma unroll
                for (int nf = 0; nf < 8; nf++)
                    mma_tf32(acc[mf][nf], af[mf], bf[nf]);
        }

        if (i + 1 < NC) {
            __syncthreads();
            int nb = buf ^ 1;
#pragma unroll
            for (int it = 0; it < 4; it++) {
                uint4 ta = { f2tf32(aR[it].x), f2tf32(aR[it].y),
                             f2tf32(aR[it].z), f2tf32(aR[it].w) };
                *(uint4*)(AsBuf[nb] + (aM + it*32) * GSTRA + aK4 * 4) = ta;
                uint4 tb = { f2tf32(bR[it].x), f2tf32(bR[it].y),
                             f2tf32(bR[it].z), f2tf32(bR[it].w) };
                *(uint4*)(BsBuf[nb] + (bK + it*8) * GSTRB + bN4 * 4) = tb;
            }
            __syncthreads();
        }
    }

#pragma unroll
    for (int nf = 0; nf < 8; nf++) {
        int col = bn + wN + nf * 8 + 2 * c;
        float b0 = bias[col], b1 = bias[col + 1];
#pragma unroll
        for (int mf = 0; mf < 2; mf++) {
            int row = bm + wM + mf * 16 + g;
#pragma unroll
            for (int half = 0; half < 2; half++) {
                int r = row + half * 8;
                float2 w;
                w.x = acc[mf][nf][half * 2 + 0] + b0;
                w.y = acc[mf][nf][half * 2 + 1] + b1;
                float* dst;
                if (MODE == 0) {
                    dst = C + (size_t)r * N + col;
                } else {
                    int bI = r >> 11, sI = r & 2047;
                    int hI = col >> 6, dI = col & 63;
                    dst = C + (((size_t)(bI * HH + hI) * SS + sI) * DKK + dI);
                }
                *(float2*)dst = w;
            }
        }
    }
}

// ===================================================================
// Tensor-core flash attention, tf32 mma.
// CTA: 128 q-rows, 8 warps (16 q-rows each, full 64-wide kv tile).
// Per kv tile: S = Q@K^T (mma), mask+scale, write scores from frags,
// register online softmax (quad shuffles), P->smem, O += P@V (mma).
// ===================================================================
#define AQ_STR 68
#define AK_STR 68
#define AV_STR 72
#define AP_STR 68
#define OFF_Q   0
#define OFF_K   (128*AQ_STR)              // 8704
#define OFF_V   (OFF_K + 64*AK_STR)       // 13056
#define OFF_P   (OFF_V + 64*AV_STR)       // 17664
#define OFF_MSK (OFF_P + 128*AP_STR)      // 26368
#define ATTN_SMEM_BYTES ((OFF_MSK + 64) * 4)   // 105728

__global__ __launch_bounds__(256)
void attn_mma(const float* __restrict__ qh, const float* __restrict__ kh,
              const float* __restrict__ vh, const int* __restrict__ mask,
              float* __restrict__ scores, float* __restrict__ concat)
{
    extern __shared__ uint32_t sm[];
    uint32_t* Qs = sm + OFF_Q;
    uint32_t* Ks = sm + OFF_K;
    uint32_t* Vs = sm + OFF_V;
    uint32_t* Ps = sm + OFF_P;
    int*      Mk = (int*)(sm + OFF_MSK);

    int tid = threadIdx.x, lane = tid & 31, wid = tid >> 5;
    int g = lane >> 2, c = lane & 3;
    int q0 = blockIdx.x * 128;
    int h = blockIdx.y, b = blockIdx.z;
    int wq = wid * 16;

    const float* Qb = qh + (size_t)(b * HH + h) * SS * DKK;
    const float* Kb = kh + (size_t)(b * HH + h) * SS * DKK;
    const float* Vb = vh + (size_t)(b * HH + h) * SS * DKK;
    float* scb = scores + ((size_t)(b * HH + h) * SS + q0) * SS;

    // ---- load Q tile [128][64] -> smem tf32 ----
#pragma unroll
    for (int i = 0; i < 8; i++) {
        int idx = tid + i * 256;           // float4 idx, 2048 total
        int row = idx >> 4, c4 = idx & 15;
        float4 v = *(const float4*)(Qb + (size_t)(q0 + row) * DKK + c4 * 4);
        uint4 t = { f2tf32(v.x), f2tf32(v.y), f2tf32(v.z), f2tf32(v.w) };
        *(uint4*)(Qs + row * AQ_STR + c4 * 4) = t;
    }

    float m0 = -INFINITY, m1 = -INFINITY, l0 = 0.f, l1 = 0.f;
    float o[8][4];
#pragma unroll
    for (int nf = 0; nf < 8; nf++)
#pragma unroll
        for (int r = 0; r < 4; r++) o[nf][r] = 0.f;

    int rowA = wq + g;

    for (int kv0 = 0; kv0 < SS; kv0 += 64) {
        __syncthreads();   // prev iter done reading K/V/P
        // ---- load K, V tiles [64][64] ----
#pragma unroll
        for (int i = 0; i < 4; i++) {
            int idx = tid + i * 256;       // float4 idx, 1024 total
            int row = idx >> 4, c4 = idx & 15;
            float4 kq = *(const float4*)(Kb + (size_t)(kv0 + row) * DKK + c4 * 4);
            uint4 tk = { f2tf32(kq.x), f2tf32(kq.y), f2tf32(kq.z), f2tf32(kq.w) };
            *(uint4*)(Ks + row * AK_STR + c4 * 4) = tk;
            float4 vq = *(const float4*)(Vb + (size_t)(kv0 + row) * DKK + c4 * 4);
            uint4 tv = { f2tf32(vq.x), f2tf32(vq.y), f2tf32(vq.z), f2tf32(vq.w) };
            *(uint4*)(Vs + row * AV_STR + c4 * 4) = tv;
        }
        if (tid < 64) Mk[tid] = mask[b * SS + kv0 + tid];
        __syncthreads();

        // ---- S = Q @ K^T : per warp 16q x 64kv ----
        float s[8][4];
#pragma unroll
        for (int nf = 0; nf < 8; nf++)
#pragma unroll
            for (int r = 0; r < 4; r++) s[nf][r] = 0.f;

#pragma unroll
        for (int ks = 0; ks < 8; ks++) {
            int kb = ks * 8;
            uint32_t af[4];
            af[0] = Qs[(rowA    ) * AQ_STR + kb + c];
            af[1] = Qs[(rowA + 8) * AQ_STR + kb + c];
            af[2] = Qs[(rowA    ) * AQ_STR + kb + c + 4];
            af[3] = Qs[(rowA + 8) * AQ_STR + kb + c + 4];
#pragma unroll
            for (int nf = 0; nf < 8; nf++) {
                int n = nf * 8 + g;
                uint32_t bf[2];
                bf[0] = Ks[n * AK_STR + kb + c];
                bf[1] = Ks[n * AK_STR + kb + c + 4];
                mma_tf32(s[nf], af, bf);
            }
        }

        // ---- mask + scale + write scores + row max ----
        float mx0 = -INFINITY, mx1 = -INFINITY;
#pragma unroll
        for (int nf = 0; nf < 8; nf++) {
            int col = nf * 8 + 2 * c;
            int mv0 = Mk[col], mv1 = Mk[col + 1];
            s[nf][0] = mv0 ? s[nf][0] * 0.125f : -1e9f;
            s[nf][1] = mv1 ? s[nf][1] * 0.125f : -1e9f;
            s[nf][2] = mv0 ? s[nf][2] * 0.125f : -1e9f;
            s[nf][3] = mv1 ? s[nf][3] * 0.125f : -1e9f;
            float2 w0 = { s[nf][0], s[nf][1] };
            float2 w1 = { s[nf][2], s[nf][3] };
            *(float2*)(scb + (size_t)(wq + g    ) * SS + kv0 + col) = w0;
            *(float2*)(scb + (size_t)(wq + g + 8) * SS + kv0 + col) = w1;
            mx0 = fmaxf(mx0, fmaxf(s[nf][0], s[nf][1]));
            mx1 = fmaxf(mx1, fmaxf(s[nf][2], s[nf][3]));
        }
        mx0 = fmaxf(mx0, __shfl_xor_sync(0xFFFFFFFFu, mx0, 1));
        mx0 = fmaxf(mx0, __shfl_xor_sync(0xFFFFFFFFu, mx0, 2));
        mx1 = fmaxf(mx1, __shfl_xor_sync(0xFFFFFFFFu, mx1, 1));
        mx1 = fmaxf(mx1, __shfl_xor_sync(0xFFFFFFFFu, mx1, 2));

        float mn0 = fmaxf(m0, mx0), mn1 = fmaxf(m1, mx1);
        float a0 = __expf(m0 - mn0), a1 = __expf(m1 - mn1);
        m0 = mn0; m1 = mn1;

        // ---- exp + row sums + store P (tf32) to smem ----
        float sum0 = 0.f, sum1 = 0.f;
#pragma unroll
        for (int nf = 0; nf < 8; nf++) {
            float p0 = __expf(s[nf][0] - mn0);
            float p1 = __expf(s[nf][1] - mn0);
            float p2 = __expf(s[nf][2] - mn1);
            float p3 = __expf(s[nf][3] - mn1);
            sum0 += p0 + p1;
            sum1 += p2 + p3;
            int col = nf * 8 + 2 * c;
            uint2 u0 = { f2tf32(p0), f2tf32(p1) };
            uint2 u1 = { f2tf32(p2), f2tf32(p3) };
            *(uint2*)(Ps + (wq + g    ) * AP_STR + col) = u0;
            *(uint2*)(Ps + (wq + g + 8) * AP_STR + col) = u1;
        }
        sum0 += __shfl_xor_sync(0xFFFFFFFFu, sum0, 1);
        sum0 += __shfl_xor_sync(0xFFFFFFFFu, sum0, 2);
        sum1 += __shfl_xor_sync(0xFFFFFFFFu, sum1, 1);
        sum1 += __shfl_xor_sync(0xFFFFFFFFu, sum1, 2);
        l0 = l0 * a0 + sum0;
        l1 = l1 * a1 + sum1;

        // ---- rescale O ----
#pragma unroll
        for (int nf = 0; nf < 8; nf++) {
            o[nf][0] *= a0; o[nf][1] *= a0;
            o[nf][2] *= a1; o[nf][3] *= a1;
        }
        __syncthreads();   // P fully written

        // ---- O += P @ V : M=16q, N=64d, K=64kv ----
#pragma unroll
        for (int ks = 0; ks < 8; ks++) {
            int kb = ks * 8;
            uint32_t af[4];
            af[0] = Ps[(rowA    ) * AP_STR + kb + c];
            af[1] = Ps[(rowA + 8) * AP_STR + kb + c];
            af[2] = Ps[(rowA    ) * AP_STR + kb + c + 4];
            af[3] = Ps[(rowA + 8) * AP_STR + kb + c + 4];
#pragma unroll
            for (int nf = 0; nf < 8; nf++) {
                int n = nf * 8 + g;
                uint32_t bf[2];
                bf[0] = Vs[(kb + c    ) * AV_STR + n];
                bf[1] = Vs[(kb + c + 4) * AV_STR + n];
                mma_tf32(o[nf], af, bf);
            }
        }
    }

    // ---- finalize: /l, write concat ----
    float inv0 = 1.f / l0, inv1 = 1.f / l1;
#pragma unroll
    for (int nf = 0; nf < 8; nf++) {
        int d = nf * 8 + 2 * c;
        float2 w0 = { o[nf][0] * inv0, o[nf][1] * inv0 };
        float2 w1 = { o[nf][2] * inv1, o[nf][3] * inv1 };
        *(float2*)(concat + (size_t)(b * SS + q0 + wq + g    ) * HD + h * DKK + d) = w0;
        *(float2*)(concat + (size_t)(b * SS + q0 + wq + g + 8) * HD + h * DKK + d) = w1;
    }
}

// ===================================================================
extern "C" void kernel_launch(void* const* d_in, const int* in_sizes, int n_in,
                              void* d_out, int out_size)
{
    const float* q   = (const float*)d_in[0];
    const float* k   = (const float*)d_in[1];
    const float* v   = (const float*)d_in[2];
    const int*   msk = (const int*)  d_in[3];
    const float* Wq  = (const float*)d_in[4];
    const float* bq  = (const float*)d_in[5];
    const float* Wk  = (const float*)d_in[6];
    const float* bk  = (const float*)d_in[7];
    const float* Wv  = (const float*)d_in[8];
    const float* bv  = (const float*)d_in[9];
    const float* Wo  = (const float*)d_in[10];
    const float* bo  = (const float*)d_in[11];

    float* out    = (float*)d_out;              // (B,S,E)
    float* scores = out + (size_t)BB * SS * EE; // (B,H,S,S)

    float *p_qh, *p_kh, *p_vh, *p_cc;
    cudaGetSymbolAddress((void**)&p_qh, g_qh);
    cudaGetSymbolAddress((void**)&p_kh, g_kh);
    cudaGetSymbolAddress((void**)&p_vh, g_vh);
    cudaGetSymbolAddress((void**)&p_cc, g_concat);

    cudaFuncSetAttribute(gemm_mma<0>, cudaFuncAttributeMaxDynamicSharedMemorySize,
                         GEMM_SMEM_BYTES);
    cudaFuncSetAttribute(gemm_mma<1>, cudaFuncAttributeMaxDynamicSharedMemorySize,
                         GEMM_SMEM_BYTES);
    cudaFuncSetAttribute(attn_mma, cudaFuncAttributeMaxDynamicSharedMemorySize,
                         ATTN_SMEM_BYTES);

    dim3 gProj(HD / 128, (BB * SS) / 128);  // (8, 32)
    gemm_mma<1><<<gProj, 256, GEMM_SMEM_BYTES>>>(q, Wq, bq, p_qh, BB * SS, HD, EE);
    gemm_mma<1><<<gProj, 256, GEMM_SMEM_BYTES>>>(k, Wk, bk, p_kh, BB * SS, HD, EE);
    gemm_mma<1><<<gProj, 256, GEMM_SMEM_BYTES>>>(v, Wv, bv, p_vh, BB * SS, HD, EE);

    dim3 gAttn(SS / 128, HH, BB);           // (16, 16, 2)
    attn_mma<<<gAttn, 256, ATTN_SMEM_BYTES>>>(p_qh, p_kh, p_vh, msk, scores, p_cc);

    dim3 gOut(EE / 128, (BB * SS) / 128);   // (8, 32)
    gemm_mma<0><<<gOut, 256, GEMM_SMEM_BYTES>>>(p_cc, Wo, bo, out, BB * SS, EE, HD);
}

// round 5
// speedup vs baseline: 2.9514x; 1.0226x over previous
#include <cuda_runtime.h>
#include <math.h>
#include <stdint.h>

#define BB 2
#define SS 2048
#define EE 1024
#define HH 16
#define DKK 64
#define HD (HH*DKK)   // 1024

// -------- scratch (allocation-free rule: __device__ globals) --------
__device__ float g_qh[BB*HH*SS*DKK];   // (B,H,S,DK)
__device__ float g_kh[BB*HH*SS*DKK];
__device__ float g_vh[BB*HH*SS*DKK];
__device__ float g_concat[BB*SS*HD];   // (B*S, H*DK)

// ===================================================================
// mma.sync tf32 helpers (baseline PTX, works on compute_103)
// ===================================================================
__device__ __forceinline__ uint32_t f2tf32(float f) {
    uint32_t r;
    asm("cvt.rna.tf32.f32 %0, %1;" : "=r"(r) : "f"(f));
    return r;
}

__device__ __forceinline__ void mma_tf32(float* d, const uint32_t* a,
                                         const uint32_t* b) {
    asm volatile(
        "mma.sync.aligned.m16n8k8.row.col.f32.tf32.tf32.f32 "
        "{%0,%1,%2,%3}, {%4,%5,%6,%7}, {%8,%9}, {%0,%1,%2,%3};"
        : "+f"(d[0]), "+f"(d[1]), "+f"(d[2]), "+f"(d[3])
        : "r"(a[0]), "r"(a[1]), "r"(a[2]), "r"(a[3]),
          "r"(b[0]), "r"(b[1]));
}

// ===================================================================
// tf32 tensor-core GEMM (unchanged from R3 — verified)
// ===================================================================
#define GSTRA 44
#define GSTRB 136
#define ASZ (128*GSTRA)
#define BSZ (32*GSTRB)
#define GEMM_SMEM_BYTES ((2*ASZ + 2*BSZ) * 4)   // 79872

template<int MODE>
__global__ __launch_bounds__(256)
void gemm_mma(const float* __restrict__ A, const float* __restrict__ W,
              const float* __restrict__ bias, float* __restrict__ C,
              int M, int N, int K)
{
    extern __shared__ uint32_t sm[];
    uint32_t* AsBuf[2] = { sm,           sm + ASZ };
    uint32_t* BsBuf[2] = { sm + 2*ASZ,   sm + 2*ASZ + BSZ };

    int tid = threadIdx.x, lane = tid & 31, wid = tid >> 5;
    int bm = blockIdx.y * 128, bn = blockIdx.x * 128;
    int wM = (wid >> 1) * 32, wN = (wid & 1) * 64;
    int g = lane >> 2, c = lane & 3;

    float acc[2][8][4];
#pragma unroll
    for (int mf = 0; mf < 2; mf++)
#pragma unroll
        for (int nf = 0; nf < 8; nf++)
#pragma unroll
            for (int r = 0; r < 4; r++) acc[mf][nf][r] = 0.f;

    const int NC = K / 32;
    int aM = tid >> 3, aK4 = tid & 7;
    int bK = tid >> 5, bN4 = tid & 31;
    float4 aR[4], bR[4];

#pragma unroll
    for (int it = 0; it < 4; it++) {
        aR[it] = *(const float4*)(A + (size_t)(bm + aM + it*32) * K + aK4 * 4);
        bR[it] = *(const float4*)(W + (size_t)(bK + it*8) * N + bn + bN4 * 4);
    }
#pragma unroll
    for (int it = 0; it < 4; it++) {
        uint4 ta = { f2tf32(aR[it].x), f2tf32(aR[it].y),
                     f2tf32(aR[it].z), f2tf32(aR[it].w) };
        *(uint4*)(AsBuf[0] + (aM + it*32) * GSTRA + aK4 * 4) = ta;
        uint4 tb = { f2tf32(bR[it].x), f2tf32(bR[it].y),
                     f2tf32(bR[it].z), f2tf32(bR[it].w) };
        *(uint4*)(BsBuf[0] + (bK + it*8) * GSTRB + bN4 * 4) = tb;
    }
    __syncthreads();

    for (int i = 0; i < NC; i++) {
        int buf = i & 1;
        if (i + 1 < NC) {
#pragma unroll
            for (int it = 0; it < 4; it++) {
                aR[it] = *(const float4*)(A + (size_t)(bm + aM + it*32) * K
                                          + (i+1) * 32 + aK4 * 4);
                bR[it] = *(const float4*)(W + (size_t)((i+1) * 32 + bK + it*8) * N
                                          + bn + bN4 * 4);
            }
        }

        const uint32_t* as = AsBuf[buf];
        const uint32_t* bs = BsBuf[buf];
#pragma unroll
        for (int ks = 0; ks < 4; ks++) {
            int kb = ks * 8;
            uint32_t af[2][4], bf[8][2];
#pragma unroll
            for (int mf = 0; mf < 2; mf++) {
                int m = wM + mf * 16 + g;
                af[mf][0] = as[(m    ) * GSTRA + kb + c];
                af[mf][1] = as[(m + 8) * GSTRA + kb + c];
                af[mf][2] = as[(m    ) * GSTRA + kb + c + 4];
                af[mf][3] = as[(m + 8) * GSTRA + kb + c + 4];
            }
#pragma unroll
            for (int nf = 0; nf < 8; nf++) {
                int n = wN + nf * 8 + g;
                bf[nf][0] = bs[(kb + c    ) * GSTRB + n];
                bf[nf][1] = bs[(kb + c + 4) * GSTRB + n];
            }
#pragma unroll
            for (int mf = 0; mf < 2; mf++)
#pragma unroll
                for (int nf = 0; nf < 8; nf++)
                    mma_tf32(acc[mf][nf], af[mf], bf[nf]);
        }

        if (i + 1 < NC) {
            __syncthreads();
            int nb = buf ^ 1;
#pragma unroll
            for (int it = 0; it < 4; it++) {
                uint4 ta = { f2tf32(aR[it].x), f2tf32(aR[it].y),
                             f2tf32(aR[it].z), f2tf32(aR[it].w) };
                *(uint4*)(AsBuf[nb] + (aM + it*32) * GSTRA + aK4 * 4) = ta;
                uint4 tb = { f2tf32(bR[it].x), f2tf32(bR[it].y),
                             f2tf32(bR[it].z), f2tf32(bR[it].w) };
                *(uint4*)(BsBuf[nb] + (bK + it*8) * GSTRB + bN4 * 4) = tb;
            }
            __syncthreads();
        }
    }

#pragma unroll
    for (int nf = 0; nf < 8; nf++) {
        int col = bn + wN + nf * 8 + 2 * c;
        float b0 = bias[col], b1 = bias[col + 1];
#pragma unroll
        for (int mf = 0; mf < 2; mf++) {
            int row = bm + wM + mf * 16 + g;
#pragma unroll
            for (int half = 0; half < 2; half++) {
                int r = row + half * 8;
                float2 w;
                w.x = acc[mf][nf][half * 2 + 0] + b0;
                w.y = acc[mf][nf][half * 2 + 1] + b1;
                float* dst;
                if (MODE == 0) {
                    dst = C + (size_t)r * N + col;
                } else {
                    int bI = r >> 11, sI = r & 2047;
                    int hI = col >> 6, dI = col & 63;
                    dst = C + (((size_t)(bI * HH + hI) * SS + sI) * DKK + dI);
                }
                *(float2*)dst = w;
            }
        }
    }
}

// ===================================================================
// Tensor-core flash attention v2.
//  - Q/K smem: column-pair interleaved so frag pairs (c, c+4) are
//    adjacent -> all frag loads are conflict-free LDS.64.
//  - V smem: transposed (d-major), kv interleaved + XOR swizzle.
//  - P never goes to smem: S-accum frags are reshaped to A-frag
//    layout with quad shuffles (exact), saving 64KB/tile + 1 sync.
// Column interleave within an 8-group: pos<4 -> 2*pos, else 2*(pos-4)+1
// ===================================================================
#define QSTR 72
#define OFF_K2   (128*QSTR)               // 9216
#define OFF_V2   (OFF_K2 + 64*QSTR)       // 13824
#define OFF_MSK2 (OFF_V2 + 64*QSTR)       // 18432
#define ATTN_SMEM_BYTES ((OFF_MSK2 + 64) * 4)   // 73984

__global__ __launch_bounds__(256, 2)
void attn_mma(const float* __restrict__ qh, const float* __restrict__ kh,
              const float* __restrict__ vh, const int* __restrict__ mask,
              float* __restrict__ scores, float* __restrict__ concat)
{
    extern __shared__ uint32_t sm[];
    uint32_t* Qs = sm;
    uint32_t* Ks = sm + OFF_K2;
    uint32_t* Vt = sm + OFF_V2;
    int*      Mk = (int*)(sm + OFF_MSK2);

    int tid = threadIdx.x, lane = tid & 31, wid = tid >> 5;
    int g = lane >> 2, c = lane & 3;
    int q0 = blockIdx.x * 128;
    int h = blockIdx.y, b = blockIdx.z;
    int wq = wid * 16;

    const float* Qb = qh + (size_t)(b * HH + h) * SS * DKK;
    const float* Kb = kh + (size_t)(b * HH + h) * SS * DKK;
    const float* Vb = vh + (size_t)(b * HH + h) * SS * DKK;
    float* scb = scores + ((size_t)(b * HH + h) * SS + q0) * SS;

    // ---- load Q tile [128][64] -> smem tf32, interleaved cols ----
#pragma unroll
    for (int i = 0; i < 8; i++) {
        int idx = tid + i * 256;
        int row = idx >> 4, c4 = idx & 15;
        float4 v = *(const float4*)(Qb + (size_t)(q0 + row) * DKK + c4 * 4);
        uint32_t* dst = Qs + row * QSTR + (c4 >> 1) * 8 + (c4 & 1);
        dst[0] = f2tf32(v.x); dst[2] = f2tf32(v.y);
        dst[4] = f2tf32(v.z); dst[6] = f2tf32(v.w);
    }

    float m0 = -INFINITY, m1 = -INFINITY, l0 = 0.f, l1 = 0.f;
    float o[8][4];
#pragma unroll
    for (int nf = 0; nf < 8; nf++)
#pragma unroll
        for (int r = 0; r < 4; r++) o[nf][r] = 0.f;

    int rowA = wq + g;
    int vD = tid & 63, vKb = (tid >> 6) * 16;     // V transpose mapping
    int qb = lane & 28;                            // quad base lane

    for (int kv0 = 0; kv0 < SS; kv0 += 64) {
        __syncthreads();   // prev iter done reading K/V
        // ---- K tile [64][64] interleaved ----
#pragma unroll
        for (int i = 0; i < 4; i++) {
            int idx = tid + i * 256;
            int row = idx >> 4, c4 = idx & 15;
            float4 kq = *(const float4*)(Kb + (size_t)(kv0 + row) * DKK + c4 * 4);
            uint32_t* dst = Ks + row * QSTR + (c4 >> 1) * 8 + (c4 & 1);
            dst[0] = f2tf32(kq.x); dst[2] = f2tf32(kq.y);
            dst[4] = f2tf32(kq.z); dst[6] = f2tf32(kq.w);
        }
        // ---- V tile transposed: Vt[d][kv], kv interleaved + swizzle ----
        {
            int swzD = ((vD >> 2) & 3) << 1;
            uint32_t* vrow = Vt + vD * QSTR;
#pragma unroll
            for (int j = 0; j < 16; j++) {
                int kv = vKb + j;
                float vv = Vb[(size_t)(kv0 + kv) * DKK + vD];
                int pos = kv & 7;
                int il = (pos < 4) ? 2 * pos : 2 * (pos - 4) + 1;
                vrow[(kv >> 3) * 8 + (il ^ swzD)] = f2tf32(vv);
            }
        }
        if (tid < 64) Mk[tid] = mask[b * SS + kv0 + tid];
        __syncthreads();

        // ---- S = Q @ K^T : per warp 16q x 64kv ----
        float s[8][4];
#pragma unroll
        for (int nf = 0; nf < 8; nf++)
#pragma unroll
            for (int r = 0; r < 4; r++) s[nf][r] = 0.f;

#pragma unroll
        for (int ks = 0; ks < 8; ks++) {
            const uint32_t* qp = Qs + rowA * QSTR + ks * 8 + 2 * c;
            uint2 a01 = *(const uint2*)qp;
            uint2 a23 = *(const uint2*)(qp + 8 * QSTR);
            uint32_t af[4] = { a01.x, a23.x, a01.y, a23.y };
#pragma unroll
            for (int nf = 0; nf < 8; nf++) {
                int n = nf * 8 + g;
                uint2 bu = *(const uint2*)(Ks + n * QSTR + ks * 8 + 2 * c);
                uint32_t bf[2] = { bu.x, bu.y };
                mma_tf32(s[nf], af, bf);
            }
        }

        // ---- mask + scale + write scores + row max ----
        float mx0 = -INFINITY, mx1 = -INFINITY;
#pragma unroll
        for (int nf = 0; nf < 8; nf++) {
            int col = nf * 8 + 2 * c;
            int2 mv = *(const int2*)(Mk + col);
            s[nf][0] = mv.x ? s[nf][0] * 0.125f : -1e9f;
            s[nf][1] = mv.y ? s[nf][1] * 0.125f : -1e9f;
            s[nf][2] = mv.x ? s[nf][2] * 0.125f : -1e9f;
            s[nf][3] = mv.y ? s[nf][3] * 0.125f : -1e9f;
            float2 w0 = { s[nf][0], s[nf][1] };
            float2 w1 = { s[nf][2], s[nf][3] };
            *(float2*)(scb + (size_t)(rowA    ) * SS + kv0 + col) = w0;
            *(float2*)(scb + (size_t)(rowA + 8) * SS + kv0 + col) = w1;
            mx0 = fmaxf(mx0, fmaxf(s[nf][0], s[nf][1]));
            mx1 = fmaxf(mx1, fmaxf(s[nf][2], s[nf][3]));
        }
        mx0 = fmaxf(mx0, __shfl_xor_sync(0xFFFFFFFFu, mx0, 1));
        mx0 = fmaxf(mx0, __shfl_xor_sync(0xFFFFFFFFu, mx0, 2));
        mx1 = fmaxf(mx1, __shfl_xor_sync(0xFFFFFFFFu, mx1, 1));
        mx1 = fmaxf(mx1, __shfl_xor_sync(0xFFFFFFFFu, mx1, 2));

        float mn0 = fmaxf(m0, mx0), mn1 = fmaxf(m1, mx1);
        float a0 = __expf(m0 - mn0), a1 = __expf(m1 - mn1);
        m0 = mn0; m1 = mn1;

        // ---- exp + row sums, convert P to tf32 bits in-place ----
        float sum0 = 0.f, sum1 = 0.f;
#pragma unroll
        for (int nf = 0; nf < 8; nf++) {
            float p0 = __expf(s[nf][0] - mn0);
            float p1 = __expf(s[nf][1] - mn0);
            float p2 = __expf(s[nf][2] - mn1);
            float p3 = __expf(s[nf][3] - mn1);
            sum0 += p0 + p1;
            sum1 += p2 + p3;
            s[nf][0] = __uint_as_float(f2tf32(p0));
            s[nf][1] = __uint_as_float(f2tf32(p1));
            s[nf][2] = __uint_as_float(f2tf32(p2));
            s[nf][3] = __uint_as_float(f2tf32(p3));
        }
        sum0 += __shfl_xor_sync(0xFFFFFFFFu, sum0, 1);
        sum0 += __shfl_xor_sync(0xFFFFFFFFu, sum0, 2);
        sum1 += __shfl_xor_sync(0xFFFFFFFFu, sum1, 1);
        sum1 += __shfl_xor_sync(0xFFFFFFFFu, sum1, 2);
        l0 = l0 * a0 + sum0;
        l1 = l1 * a1 + sum1;

        // ---- rescale O ----
#pragma unroll
        for (int nf = 0; nf < 8; nf++) {
            o[nf][0] *= a0; o[nf][1] *= a0;
            o[nf][2] *= a1; o[nf][3] *= a1;
        }

        // ---- O += P @ V : P A-frags built by quad shuffles ----
        int src  = qb + (c >> 1);
        int src2 = src + 2;
        bool odd = (c & 1);
#pragma unroll
        for (int ks = 0; ks < 8; ks++) {
            float x0 = __shfl_sync(0xFFFFFFFFu, s[ks][0], src);
            float x1 = __shfl_sync(0xFFFFFFFFu, s[ks][1], src);
            float x2 = __shfl_sync(0xFFFFFFFFu, s[ks][2], src);
            float x3 = __shfl_sync(0xFFFFFFFFu, s[ks][3], src);
            float y0 = __shfl_sync(0xFFFFFFFFu, s[ks][0], src2);
            float y1 = __shfl_sync(0xFFFFFFFFu, s[ks][1], src2);
            float y2 = __shfl_sync(0xFFFFFFFFu, s[ks][2], src2);
            float y3 = __shfl_sync(0xFFFFFFFFu, s[ks][3], src2);
            uint32_t af[4];
            af[0] = __float_as_uint(odd ? x1 : x0);
            af[1] = __float_as_uint(odd ? x3 : x2);
            af[2] = __float_as_uint(odd ? y1 : y0);
            af[3] = __float_as_uint(odd ? y3 : y2);
#pragma unroll
            for (int nf = 0; nf < 8; nf++) {
                int n = nf * 8 + g;
                int swz = ((n >> 2) & 3) << 1;
                uint2 bu = *(const uint2*)(Vt + n * QSTR + ks * 8 + ((2 * c) ^ swz));
                uint32_t bf[2] = { bu.x, bu.y };
                mma_tf32(o[nf], af, bf);
            }
        }
    }

    // ---- finalize: /l, write concat ----
    float inv0 = 1.f / l0, inv1 = 1.f / l1;
#pragma unroll
    for (int nf = 0; nf < 8; nf++) {
        int d = nf * 8 + 2 * c;
        float2 w0 = { o[nf][0] * inv0, o[nf][1] * inv0 };
        float2 w1 = { o[nf][2] * inv1, o[nf][3] * inv1 };
        *(float2*)(concat + (size_t)(b * SS + q0 + rowA    ) * HD + h * DKK + d) = w0;
        *(float2*)(concat + (size_t)(b * SS + q0 + rowA + 8) * HD + h * DKK + d) = w1;
    }
}

// ===================================================================
extern "C" void kernel_launch(void* const* d_in, const int* in_sizes, int n_in,
                              void* d_out, int out_size)
{
    const float* q   = (const float*)d_in[0];
    const float* k   = (const float*)d_in[1];
    const float* v   = (const float*)d_in[2];
    const int*   msk = (const int*)  d_in[3];
    const float* Wq  = (const float*)d_in[4];
    const float* bq  = (const float*)d_in[5];
    const float* Wk  = (const float*)d_in[6];
    const float* bk  = (const float*)d_in[7];
    const float* Wv  = (const float*)d_in[8];
    const float* bv  = (const float*)d_in[9];
    const float* Wo  = (const float*)d_in[10];
    const float* bo  = (const float*)d_in[11];

    float* out    = (float*)d_out;              // (B,S,E)
    float* scores = out + (size_t)BB * SS * EE; // (B,H,S,S)

    float *p_qh, *p_kh, *p_vh, *p_cc;
    cudaGetSymbolAddress((void**)&p_qh, g_qh);
    cudaGetSymbolAddress((void**)&p_kh, g_kh);
    cudaGetSymbolAddress((void**)&p_vh, g_vh);
    cudaGetSymbolAddress((void**)&p_cc, g_concat);

    cudaFuncSetAttribute(gemm_mma<0>, cudaFuncAttributeMaxDynamicSharedMemorySize,
                         GEMM_SMEM_BYTES);
    cudaFuncSetAttribute(gemm_mma<1>, cudaFuncAttributeMaxDynamicSharedMemorySize,
                         GEMM_SMEM_BYTES);
    cudaFuncSetAttribute(attn_mma, cudaFuncAttributeMaxDynamicSharedMemorySize,
                         ATTN_SMEM_BYTES);

    dim3 gProj(HD / 128, (BB * SS) / 128);  // (8, 32)
    gemm_mma<1><<<gProj, 256, GEMM_SMEM_BYTES>>>(q, Wq, bq, p_qh, BB * SS, HD, EE);
    gemm_mma<1><<<gProj, 256, GEMM_SMEM_BYTES>>>(k, Wk, bk, p_kh, BB * SS, HD, EE);
    gemm_mma<1><<<gProj, 256, GEMM_SMEM_BYTES>>>(v, Wv, bv, p_vh, BB * SS, HD, EE);

    dim3 gAttn(SS / 128, HH, BB);           // (16, 16, 2)
    attn_mma<<<gAttn, 256, ATTN_SMEM_BYTES>>>(p_qh, p_kh, p_vh, msk, scores, p_cc);

    dim3 gOut(EE / 128, (BB * SS) / 128);   // (8, 32)
    gemm_mma<0><<<gOut, 256, GEMM_SMEM_BYTES>>>(p_cc, Wo, bo, out, BB * SS, EE, HD);
}